// round 8
// baseline (speedup 1.0000x reference)
#include <cuda_runtime.h>
#include <math.h>

#define BATCH 4096
#define DIN   64
#define HID   256
#define NB    30
#define NDOF  7
#define OUTC  217
#define NS    51
#define DTC   0.002f
#define AZBZ  56.25f
// ln(float(0.998)) and ln(0.985)
#define LNX   (-0.0020019769f)
#define LNLAM (-0.015113638f)
#define GW    501
#define BO    (BATCH * OUTC)

__device__ float g_feat[BATCH * HID];
__device__ float g_out217[2 * BO];     // two split-K partials
__device__ float g_coef[NS * 33];

typedef unsigned long long ull;
__device__ __forceinline__ void fma2(ull& d, ull a, ull b) {
    asm("fma.rn.f32x2 %0, %1, %2, %0;" : "+l"(d) : "l"(a), "l"(b));
}
__device__ __forceinline__ float lo32(ull v) { return __uint_as_float((unsigned)v); }
__device__ __forceinline__ float hi32(ull v) { return __uint_as_float((unsigned)(v >> 32)); }

// ---------------------------------------------------------------------------
// Fused forcing + coefficient kernel (one block per sample; side stream).
// ---------------------------------------------------------------------------
__global__ __launch_bounds__(256) void coef_kernel(const float* __restrict__ c,
                                                   const float* __restrict__ h) {
    extern __shared__ float sm[];
    float* g  = sm;                 // [NB][GW]
    float* kw = g + NB * GW;        // [GW]
    float* sc = kw + GW;            // [NB]
    float* sh = sc + NB;            // [NB]

    const int tid = threadIdx.x;
    const int s = blockIdx.x;
    const int T = s * 10;

    if (tid < NB) { sc[tid] = c[tid]; sh[tid] = h[tid]; }
    for (int k = tid; k <= T; k += 256)
        kw[k] = (k == 0) ? 0.f : (float)k * expf(LNLAM * (float)(k - 1));
    __syncthreads();

    for (int i = tid + 1; i < T; i += 256) {
        float x = expf(LNX * (float)i);
        float psi[NB];
        float S = 0.f;
#pragma unroll
        for (int n = 0; n < NB; n++) {
            float d = x - sc[n];
            float p = expf(-sh[n] * d * d);
            psi[n] = p;
            S += p;
        }
        float scale = x / S;
#pragma unroll
        for (int n = 0; n < NB; n++) g[n * GW + i] = psi[n] * scale;
    }
    __syncthreads();

    const int n = tid >> 3;
    const int part = tid & 7;
    float acc = 0.f;
    if (n < NB) {
        const float* gn = g + n * GW;
        for (int k = part; k < T; k += 8) acc += kw[k] * gn[T - k];
    } else if (n == NB) {
        for (int k = part; k < T; k += 8) acc += kw[k];
    }
    acc += __shfl_down_sync(0xffffffffu, acc, 4, 8);
    acc += __shfl_down_sync(0xffffffffu, acc, 2, 8);
    acc += __shfl_down_sync(0xffffffffu, acc, 1, 8);

    if (part == 0) {
        if (n < NB)       g_coef[s * 33 + 3 + n] = (DTC * DTC) * acc;
        else if (n == NB) g_coef[s * 33 + 2]     = AZBZ * (DTC * DTC) * acc;
    }
    if (tid == 254) g_coef[s * 33 + 0] = 0.05f * DTC * kw[T];
    if (tid == 255) g_coef[s * 33 + 1] = expf(LNLAM * (float)T) + 0.015f * kw[T];
}

// ---------------------------------------------------------------------------
// GEMM1: feat = tanh(x @ W_pt + b_pt). M=4096,N=256,K=64.
// ---------------------------------------------------------------------------
__global__ __launch_bounds__(256) void gemm1_kernel(const float* __restrict__ X,
                                                    const float* __restrict__ Wp,
                                                    const float* __restrict__ bp) {
    __shared__ __align__(16) float  As[64][68];   // [k][m]
    __shared__ float2 Bs[64][66];                 // [k][n] duplicated
    const int tid = threadIdx.x;
    const int bm = blockIdx.x * 64;
    const int bn = blockIdx.y * 64;

#pragma unroll
    for (int it = 0; it < 4; it++) {
        int id = tid + it * 256;
        int m = id >> 4, k4 = (id & 15) << 2;
        float4 v = *reinterpret_cast<const float4*>(X + (bm + m) * DIN + k4);
        As[k4 + 0][m] = v.x; As[k4 + 1][m] = v.y;
        As[k4 + 2][m] = v.z; As[k4 + 3][m] = v.w;
    }
#pragma unroll
    for (int it = 0; it < 4; it++) {
        int id = tid + it * 256;
        int k = id >> 4, n4 = (id & 15) << 2;
        float4 v = *reinterpret_cast<const float4*>(Wp + k * HID + bn + n4);
        Bs[k][n4 + 0] = make_float2(v.x, v.x);
        Bs[k][n4 + 1] = make_float2(v.y, v.y);
        Bs[k][n4 + 2] = make_float2(v.z, v.z);
        Bs[k][n4 + 3] = make_float2(v.w, v.w);
    }
    __syncthreads();

    const int ty = tid >> 4, tx = tid & 15;
    ull acc[2][4];
#pragma unroll
    for (int i = 0; i < 2; i++)
#pragma unroll
        for (int j = 0; j < 4; j++) acc[i][j] = 0ull;

#pragma unroll
    for (int k = 0; k < 64; k++) {
        float4 a = *reinterpret_cast<const float4*>(&As[k][ty * 4]);
        ull p0 = *reinterpret_cast<const ull*>(&a.x);
        ull p1 = *reinterpret_cast<const ull*>(&a.z);
#pragma unroll
        for (int j = 0; j < 4; j++) {
            ull b = *reinterpret_cast<const ull*>(&Bs[k][tx + 16 * j]);
            fma2(acc[0][j], p0, b);
            fma2(acc[1][j], p1, b);
        }
    }

#pragma unroll
    for (int j = 0; j < 4; j++) {
        int col = bn + tx + 16 * j;
        float bb = bp[col];
        int r = bm + ty * 4;
        g_feat[(r + 0) * HID + col] = tanhf(lo32(acc[0][j]) + bb);
        g_feat[(r + 1) * HID + col] = tanhf(hi32(acc[0][j]) + bb);
        g_feat[(r + 2) * HID + col] = tanhf(lo32(acc[1][j]) + bb);
        g_feat[(r + 3) * HID + col] = tanhf(hi32(acc[1][j]) + bb);
    }
}

// ---------------------------------------------------------------------------
// GEMM2 (split-K x2): partial[z] = feat[:, z*128:(z+1)*128] @ W_last[z half].
// ---------------------------------------------------------------------------
__global__ __launch_bounds__(256) void gemm2_kernel(const float* __restrict__ Wl,
                                                    const float* __restrict__ bl) {
    __shared__ __align__(16) float  As[32][68];   // [k][m]
    __shared__ float2 Bs[32][114];                // [k][n] duplicated
    const int tid = threadIdx.x;
    const int bm = blockIdx.x * 64;
    const int bn = blockIdx.y * 112;
    const int z  = blockIdx.z;
    const int kbase = z * 128;
    const int ty = tid >> 4, tx = tid & 15;

    const int am = tid >> 3;
    const int ak4 = (tid & 7) << 2;

    float4 ra[2];
    float rb[14];

#pragma unroll
    for (int it = 0; it < 2; it++)
        ra[it] = *reinterpret_cast<const float4*>(
            g_feat + (bm + am + it * 32) * HID + kbase + ak4);
#pragma unroll
    for (int it = 0; it < 14; it++) {
        int id = tid + it * 256;
        int kk = id / 112, cc = id - kk * 112;
        rb[it] = (bn + cc < OUTC) ? Wl[(kbase + kk) * OUTC + bn + cc] : 0.f;
    }

    ull acc[2][7];
#pragma unroll
    for (int i = 0; i < 2; i++)
#pragma unroll
        for (int j = 0; j < 7; j++) acc[i][j] = 0ull;

    for (int k0 = 0; k0 < 128; k0 += 32) {
#pragma unroll
        for (int it = 0; it < 2; it++) {
            int m = am + it * 32;
            As[ak4 + 0][m] = ra[it].x; As[ak4 + 1][m] = ra[it].y;
            As[ak4 + 2][m] = ra[it].z; As[ak4 + 3][m] = ra[it].w;
        }
#pragma unroll
        for (int it = 0; it < 14; it++) {
            int id = tid + it * 256;
            int kk = id / 112, cc = id - kk * 112;
            Bs[kk][cc] = make_float2(rb[it], rb[it]);
        }
        __syncthreads();

        if (k0 + 32 < 128) {
#pragma unroll
            for (int it = 0; it < 2; it++)
                ra[it] = *reinterpret_cast<const float4*>(
                    g_feat + (bm + am + it * 32) * HID + kbase + k0 + 32 + ak4);
#pragma unroll
            for (int it = 0; it < 14; it++) {
                int id = tid + it * 256;
                int kk = id / 112, cc = id - kk * 112;
                rb[it] = (bn + cc < OUTC)
                           ? Wl[(kbase + k0 + 32 + kk) * OUTC + bn + cc] : 0.f;
            }
        }

#pragma unroll
        for (int kk = 0; kk < 32; kk++) {
            float4 a = *reinterpret_cast<const float4*>(&As[kk][ty * 4]);
            ull p0 = *reinterpret_cast<const ull*>(&a.x);
            ull p1 = *reinterpret_cast<const ull*>(&a.z);
#pragma unroll
            for (int j = 0; j < 7; j++) {
                ull b = *reinterpret_cast<const ull*>(&Bs[kk][tx + 16 * j]);
                fma2(acc[0][j], p0, b);
                fma2(acc[1][j], p1, b);
            }
        }
        __syncthreads();
    }

    float* outp = g_out217 + z * BO;
#pragma unroll
    for (int j = 0; j < 7; j++) {
        int col = bn + tx + 16 * j;
        if (col < OUTC) {
            float bb = (z == 0) ? bl[col] : 0.f;
            int r = bm + ty * 4;
            outp[(r + 0) * OUTC + col] = lo32(acc[0][j]) + bb;
            outp[(r + 1) * OUTC + col] = hi32(acc[0][j]) + bb;
            outp[(r + 2) * OUTC + col] = lo32(acc[1][j]) + bb;
            outp[(r + 3) * OUTC + col] = hi32(acc[1][j]) + bb;
        }
    }
}

// ---------------------------------------------------------------------------
// Rollout v4: block = 8 contiguous batches (56 rows), 512 blocks for occupancy.
//  A: load 1736-float out217 slice (both partials summed) -> smem
//  B: build U[33][56] in smem
//  C: contraction (fma2, 2 rows x 7 samples per thread, 224/256 active)
//  D: contiguous float4 store of the block's 2856-float output slice
// ---------------------------------------------------------------------------
#define RB_BATCH 8
#define RB_ROWS  (RB_BATCH * NDOF)            // 56
#define RB_OUTF  (RB_BATCH * OUTC)            // 1736
#define RB_YF    (RB_BATCH * NS * NDOF)       // 2856
// smem floats: scfd 33*56*2=3696, su 33*56=1848, sg 56, union max(1736,2856)
#define RB_SCFD  0
#define RB_SU    3696
#define RB_SG    (3696 + 1848)                // 5544
#define RB_RG    (3696 + 1848 + 56)           // 5600 (16B aligned)
#define RB_SMEM  ((RB_RG + RB_YF) * 4)        // 33824 bytes

__global__ __launch_bounds__(256) void rollout_kernel(const float* __restrict__ state,
                                                      float* __restrict__ out) {
    extern __shared__ __align__(16) float sm[];
    float2* scfd = reinterpret_cast<float2*>(sm + RB_SCFD);   // [33][56]
    float*  su   = sm + RB_SU;                                // [33][56]
    float*  sg   = sm + RB_SG;                                // [56]
    float*  so   = sm + RB_RG;                                // [1736]
    float*  ybuf = sm + RB_RG;                                // [2856] (after B)

    const int tid = threadIdx.x;
    const int bbase = blockIdx.x * RB_BATCH;

    // coefficients (duplicated for fma2)
    for (int i = tid; i < 33 * 56; i += 256) {
        int ch = i / 56, s = i - ch * 56;
        float v = (s < NS) ? g_coef[s * 33 + ch] : 0.f;
        scfd[ch * 56 + s] = make_float2(v, v);
    }
    // A: contiguous float4 load of both partials, summed
    {
        const float4* p0 = reinterpret_cast<const float4*>(g_out217 + bbase * OUTC);
        const float4* p1 = reinterpret_cast<const float4*>(g_out217 + BO + bbase * OUTC);
        float4* d = reinterpret_cast<float4*>(so);
        for (int i = tid; i < RB_OUTF / 4; i += 256) {
            float4 a = p0[i], b = p1[i];
            d[i] = make_float4(a.x + b.x, a.y + b.y, a.z + b.z, a.w + b.w);
        }
    }
    __syncthreads();

    // mini-phase: y0 / goal / gy0
    if (tid < RB_ROWS) {
        int b = tid / NDOF, dof = tid - b * NDOF;
        float y0 = state[bbase * NDOF + tid];
        float goal = so[b * OUTC + dof];
        su[1 * RB_ROWS + tid] = y0;
        su[2 * RB_ROWS + tid] = goal;
        sg[tid] = goal - y0;
    }
    __syncthreads();

    // B: forcing channels u_n = w_n * gy0
    for (int idx = tid; idx < NB * RB_ROWS; idx += 256) {
        int n = idx / RB_ROWS, r = idx - n * RB_ROWS;
        int b = r / NDOF, dof = r - b * NDOF;
        float w = so[b * OUTC + NDOF + dof * NB + n];
        su[(3 + n) * RB_ROWS + r] = w * sg[r];
    }
    __syncthreads();

    // C: y[row][s] = alpha[s] + sum_{ch>=1} U[row][ch]*coef[s][ch]
    {
        const int rp  = tid % 28;           // row pair: rows rp*2, rp*2+1
        const int grp = tid / 28;           // sample group 0..8 (8 active)
        if (grp < 8) {
            const int s0 = grp * 7;
            const int cnt = (grp == 7) ? 2 : 7;   // 7*7=49, last group 49..50

            ull acc[7];
#pragma unroll
            for (int q = 0; q < 7; q++)
                acc[q] = *reinterpret_cast<const ull*>(&scfd[0 * 56 + s0 + q]);

#pragma unroll
            for (int ch = 1; ch < 33; ch++) {
                ull u = *reinterpret_cast<const ull*>(&su[ch * RB_ROWS + rp * 2]);
                const float2* cf = &scfd[ch * 56 + s0];
#pragma unroll
                for (int q = 0; q < 7; q++) {
                    ull b = *reinterpret_cast<const ull*>(&cf[q]);
                    fma2(acc[q], u, b);
                }
            }

#pragma unroll
            for (int p = 0; p < 2; p++) {
                int row = rp * 2 + p;
                int b = row / NDOF, dof = row - b * NDOF;
                float* yb = ybuf + b * (NS * NDOF) + dof;
#pragma unroll
                for (int q = 0; q < 7; q++) {
                    if (q < cnt) {
                        float v = p ? hi32(acc[q]) : lo32(acc[q]);
                        yb[(s0 + q) * NDOF] = v;
                    }
                }
            }
        }
    }
    __syncthreads();

    // D: contiguous float4 store of the block's output slice
    {
        const float4* s4 = reinterpret_cast<const float4*>(ybuf);
        float4* d4 = reinterpret_cast<float4*>(out + (size_t)blockIdx.x * RB_YF);
        for (int i = tid; i < RB_YF / 4; i += 256) d4[i] = s4[i];
    }
}

// ---------------------------------------------------------------------------
extern "C" void kernel_launch(void* const* d_in, const int* in_sizes, int n_in,
                              void* d_out, int out_size) {
    const float* x      = (const float*)d_in[0];
    const float* state  = (const float*)d_in[1];
    const float* W_pt   = (const float*)d_in[2];
    const float* b_pt   = (const float*)d_in[3];
    const float* W_last = (const float*)d_in[4];
    const float* b_last = (const float*)d_in[5];
    const float* c      = (const float*)d_in[6];
    const float* h      = (const float*)d_in[7];
    float* out = (float*)d_out;

    const int coef_smem = (NB * GW + GW + 2 * NB) * (int)sizeof(float);

    static cudaStream_t s2;
    static cudaEvent_t evFork, evJoin;
    static int init_done = 0;
    if (!init_done) {
        cudaFuncSetAttribute(coef_kernel, cudaFuncAttributeMaxDynamicSharedMemorySize,
                             coef_smem);
        cudaFuncSetAttribute(rollout_kernel, cudaFuncAttributeMaxDynamicSharedMemorySize,
                             RB_SMEM);
        cudaStreamCreateWithFlags(&s2, cudaStreamNonBlocking);
        cudaEventCreateWithFlags(&evFork, cudaEventDisableTiming);
        cudaEventCreateWithFlags(&evJoin, cudaEventDisableTiming);
        init_done = 1;
    }

    // fork: coef runs concurrently with the two GEMMs
    cudaEventRecord(evFork, 0);
    cudaStreamWaitEvent(s2, evFork, 0);
    coef_kernel<<<NS, 256, coef_smem, s2>>>(c, h);
    cudaEventRecord(evJoin, s2);

    gemm1_kernel<<<dim3(BATCH / 64, HID / 64), 256>>>(x, W_pt, b_pt);
    gemm2_kernel<<<dim3(BATCH / 64, 2, 2), 256>>>(W_last, b_last);

    // join: rollout needs both g_coef and g_out217 partials
    cudaStreamWaitEvent(0, evJoin, 0);
    rollout_kernel<<<BATCH / RB_BATCH, 256, RB_SMEM>>>(state, out);
}

// round 9
// speedup vs baseline: 1.0468x; 1.0468x over previous
#include <cuda_runtime.h>
#include <math.h>

#define BATCH 4096
#define DIN   64
#define HID   256
#define NB    30
#define NDOF  7
#define OUTC  217
#define NS    51
#define DTC   0.002f
#define AZBZ  56.25f
// ln(float(0.998)) and ln(0.985)
#define LNX   (-0.0020019769f)
#define LNLAM (-0.015113638f)
#define GW    501
#define BO    (BATCH * OUTC)

__device__ float g_feat[BATCH * HID];
__device__ float g_out217[2 * BO];       // two split-K partials
// coefficients, transposed [ch][slot], slot = (s/7)*8 + s%7 (groups of 7 padded
// to 8), duplicated as float2 for fma2. Padding slots never written -> stay 0
// (static zero-init of __device__ globals).
__device__ float2 g_coef_t[33 * 64];

typedef unsigned long long ull;
__device__ __forceinline__ void fma2(ull& d, ull a, ull b) {
    asm("fma.rn.f32x2 %0, %1, %2, %0;" : "+l"(d) : "l"(a), "l"(b));
}
__device__ __forceinline__ float lo32(ull v) { return __uint_as_float((unsigned)v); }
__device__ __forceinline__ float hi32(ull v) { return __uint_as_float((unsigned)(v >> 32)); }
__device__ __forceinline__ ull pack2(float x, float y) {
    ull r;
    asm("mov.b64 %0, {%1, %2};" : "=l"(r) : "f"(x), "f"(y));
    return r;
}

// ---------------------------------------------------------------------------
// Fused forcing + coefficient kernel (one block per sample; side stream).
// Writes g_coef_t[ch][slot] duplicated.
// ---------------------------------------------------------------------------
__global__ __launch_bounds__(256) void coef_kernel(const float* __restrict__ c,
                                                   const float* __restrict__ h) {
    extern __shared__ float sm[];
    float* g  = sm;                 // [NB][GW]
    float* kw = g + NB * GW;        // [GW]
    float* sc = kw + GW;            // [NB]
    float* sh = sc + NB;            // [NB]

    const int tid = threadIdx.x;
    const int s = blockIdx.x;
    const int T = s * 10;
    const int slot = (s / 7) * 8 + (s % 7);

    if (tid < NB) { sc[tid] = c[tid]; sh[tid] = h[tid]; }
    for (int k = tid; k <= T; k += 256)
        kw[k] = (k == 0) ? 0.f : (float)k * expf(LNLAM * (float)(k - 1));
    __syncthreads();

    for (int i = tid + 1; i < T; i += 256) {
        float x = expf(LNX * (float)i);
        float psi[NB];
        float S = 0.f;
#pragma unroll
        for (int n = 0; n < NB; n++) {
            float d = x - sc[n];
            float p = expf(-sh[n] * d * d);
            psi[n] = p;
            S += p;
        }
        float scale = x / S;
#pragma unroll
        for (int n = 0; n < NB; n++) g[n * GW + i] = psi[n] * scale;
    }
    __syncthreads();

    const int n = tid >> 3;
    const int part = tid & 7;
    float acc = 0.f;
    if (n < NB) {
        const float* gn = g + n * GW;
        for (int k = part; k < T; k += 8) acc += kw[k] * gn[T - k];
    } else if (n == NB) {
        for (int k = part; k < T; k += 8) acc += kw[k];
    }
    acc += __shfl_down_sync(0xffffffffu, acc, 4, 8);
    acc += __shfl_down_sync(0xffffffffu, acc, 2, 8);
    acc += __shfl_down_sync(0xffffffffu, acc, 1, 8);

    if (part == 0) {
        if (n < NB) {
            float v = (DTC * DTC) * acc;
            g_coef_t[(3 + n) * 64 + slot] = make_float2(v, v);
        } else if (n == NB) {
            float v = AZBZ * (DTC * DTC) * acc;
            g_coef_t[2 * 64 + slot] = make_float2(v, v);
        }
    }
    if (tid == 254) {
        float v = 0.05f * DTC * kw[T];
        g_coef_t[0 * 64 + slot] = make_float2(v, v);
    }
    if (tid == 255) {
        float v = expf(LNLAM * (float)T) + 0.015f * kw[T];
        g_coef_t[1 * 64 + slot] = make_float2(v, v);
    }
}

// ---------------------------------------------------------------------------
// GEMM1: feat = tanh(x @ W_pt + b_pt). M=4096,N=256,K=64.
// ---------------------------------------------------------------------------
__global__ __launch_bounds__(256) void gemm1_kernel(const float* __restrict__ X,
                                                    const float* __restrict__ Wp,
                                                    const float* __restrict__ bp) {
    __shared__ __align__(16) float  As[64][68];   // [k][m]
    __shared__ float2 Bs[64][66];                 // [k][n] duplicated
    const int tid = threadIdx.x;
    const int bm = blockIdx.x * 64;
    const int bn = blockIdx.y * 64;

#pragma unroll
    for (int it = 0; it < 4; it++) {
        int id = tid + it * 256;
        int m = id >> 4, k4 = (id & 15) << 2;
        float4 v = *reinterpret_cast<const float4*>(X + (bm + m) * DIN + k4);
        As[k4 + 0][m] = v.x; As[k4 + 1][m] = v.y;
        As[k4 + 2][m] = v.z; As[k4 + 3][m] = v.w;
    }
#pragma unroll
    for (int it = 0; it < 4; it++) {
        int id = tid + it * 256;
        int k = id >> 4, n4 = (id & 15) << 2;
        float4 v = *reinterpret_cast<const float4*>(Wp + k * HID + bn + n4);
        Bs[k][n4 + 0] = make_float2(v.x, v.x);
        Bs[k][n4 + 1] = make_float2(v.y, v.y);
        Bs[k][n4 + 2] = make_float2(v.z, v.z);
        Bs[k][n4 + 3] = make_float2(v.w, v.w);
    }
    __syncthreads();

    const int ty = tid >> 4, tx = tid & 15;
    ull acc[2][4];
#pragma unroll
    for (int i = 0; i < 2; i++)
#pragma unroll
        for (int j = 0; j < 4; j++) acc[i][j] = 0ull;

#pragma unroll
    for (int k = 0; k < 64; k++) {
        float4 a = *reinterpret_cast<const float4*>(&As[k][ty * 4]);
        ull p0 = *reinterpret_cast<const ull*>(&a.x);
        ull p1 = *reinterpret_cast<const ull*>(&a.z);
#pragma unroll
        for (int j = 0; j < 4; j++) {
            ull b = *reinterpret_cast<const ull*>(&Bs[k][tx + 16 * j]);
            fma2(acc[0][j], p0, b);
            fma2(acc[1][j], p1, b);
        }
    }

#pragma unroll
    for (int j = 0; j < 4; j++) {
        int col = bn + tx + 16 * j;
        float bb = bp[col];
        int r = bm + ty * 4;
        g_feat[(r + 0) * HID + col] = tanhf(lo32(acc[0][j]) + bb);
        g_feat[(r + 1) * HID + col] = tanhf(hi32(acc[0][j]) + bb);
        g_feat[(r + 2) * HID + col] = tanhf(lo32(acc[1][j]) + bb);
        g_feat[(r + 3) * HID + col] = tanhf(hi32(acc[1][j]) + bb);
    }
}

// ---------------------------------------------------------------------------
// GEMM2 (split-K x2): partial[z] = feat[:, z*128:(z+1)*128] @ W_last[z half].
// ---------------------------------------------------------------------------
__global__ __launch_bounds__(256) void gemm2_kernel(const float* __restrict__ Wl,
                                                    const float* __restrict__ bl) {
    __shared__ __align__(16) float  As[32][68];   // [k][m]
    __shared__ float2 Bs[32][114];                // [k][n] duplicated
    const int tid = threadIdx.x;
    const int bm = blockIdx.x * 64;
    const int bn = blockIdx.y * 112;
    const int z  = blockIdx.z;
    const int kbase = z * 128;
    const int ty = tid >> 4, tx = tid & 15;

    const int am = tid >> 3;
    const int ak4 = (tid & 7) << 2;

    float4 ra[2];
    float rb[14];

#pragma unroll
    for (int it = 0; it < 2; it++)
        ra[it] = *reinterpret_cast<const float4*>(
            g_feat + (bm + am + it * 32) * HID + kbase + ak4);
#pragma unroll
    for (int it = 0; it < 14; it++) {
        int id = tid + it * 256;
        int kk = id / 112, cc = id - kk * 112;
        rb[it] = (bn + cc < OUTC) ? Wl[(kbase + kk) * OUTC + bn + cc] : 0.f;
    }

    ull acc[2][7];
#pragma unroll
    for (int i = 0; i < 2; i++)
#pragma unroll
        for (int j = 0; j < 7; j++) acc[i][j] = 0ull;

    for (int k0 = 0; k0 < 128; k0 += 32) {
#pragma unroll
        for (int it = 0; it < 2; it++) {
            int m = am + it * 32;
            As[ak4 + 0][m] = ra[it].x; As[ak4 + 1][m] = ra[it].y;
            As[ak4 + 2][m] = ra[it].z; As[ak4 + 3][m] = ra[it].w;
        }
#pragma unroll
        for (int it = 0; it < 14; it++) {
            int id = tid + it * 256;
            int kk = id / 112, cc = id - kk * 112;
            Bs[kk][cc] = make_float2(rb[it], rb[it]);
        }
        __syncthreads();

        if (k0 + 32 < 128) {
#pragma unroll
            for (int it = 0; it < 2; it++)
                ra[it] = *reinterpret_cast<const float4*>(
                    g_feat + (bm + am + it * 32) * HID + kbase + k0 + 32 + ak4);
#pragma unroll
            for (int it = 0; it < 14; it++) {
                int id = tid + it * 256;
                int kk = id / 112, cc = id - kk * 112;
                rb[it] = (bn + cc < OUTC)
                           ? Wl[(kbase + k0 + 32 + kk) * OUTC + bn + cc] : 0.f;
            }
        }

#pragma unroll
        for (int kk = 0; kk < 32; kk++) {
            float4 a = *reinterpret_cast<const float4*>(&As[kk][ty * 4]);
            ull p0 = *reinterpret_cast<const ull*>(&a.x);
            ull p1 = *reinterpret_cast<const ull*>(&a.z);
#pragma unroll
            for (int j = 0; j < 7; j++) {
                ull b = *reinterpret_cast<const ull*>(&Bs[kk][tx + 16 * j]);
                fma2(acc[0][j], p0, b);
                fma2(acc[1][j], p1, b);
            }
        }
        __syncthreads();
    }

    float* outp = g_out217 + z * BO;
#pragma unroll
    for (int j = 0; j < 7; j++) {
        int col = bn + tx + 16 * j;
        if (col < OUTC) {
            float bb = (z == 0) ? bl[col] : 0.f;
            int r = bm + ty * 4;
            outp[(r + 0) * OUTC + col] = lo32(acc[0][j]) + bb;
            outp[(r + 1) * OUTC + col] = hi32(acc[0][j]) + bb;
            outp[(r + 2) * OUTC + col] = lo32(acc[1][j]) + bb;
            outp[(r + 3) * OUTC + col] = hi32(acc[1][j]) + bb;
        }
    }
}

// ---------------------------------------------------------------------------
// Rollout v5: block = 8 batches (56 rows), 512 blocks. Instruction-minimized:
//  - scfd fill = pure float4 copy (g_coef_t pre-transposed/duplicated/padded)
//  - U-build with per-thread constant (row, dof) and stride-constant loops
//  - C loop: per ch = 1 LDS.64 + 4 LDS.128 + 7 fma2, const-offset addressing
// ---------------------------------------------------------------------------
#define RB_BATCH 8
#define RB_ROWS  56
#define RB_OUTF  (RB_BATCH * OUTC)            // 1736
#define RB_YF    (RB_BATCH * NS * NDOF)       // 2856
// smem floats: scfd 33*64*2 = 4224 | su 33*56 = 1848 | sg 56 | so/ybuf 2856
#define RB_SU    4224
#define RB_SG    (4224 + 1848)                // 6072
#define RB_RG    (6072 + 56)                  // 6128  (6128*4 % 16 == 0)
#define RB_SMEM  ((RB_RG + RB_YF) * 4)        // 35936 bytes

__global__ __launch_bounds__(256) void rollout_kernel(const float* __restrict__ state,
                                                      float* __restrict__ out) {
    extern __shared__ __align__(16) float sm[];
    float2* scfd = reinterpret_cast<float2*>(sm);   // [33][64] slots
    float*  su   = sm + RB_SU;                      // [33][56]
    float*  sg   = sm + RB_SG;                      // [56]
    float*  so   = sm + RB_RG;                      // [1736]
    float*  ybuf = sm + RB_RG;                      // [2856] (after U build)

    const int tid = threadIdx.x;
    const int bbase = blockIdx.x * RB_BATCH;

    // scfd fill: pure vector copy, 33*64 float2 = 1056 float4
    {
        const float4* src = reinterpret_cast<const float4*>(g_coef_t);
        float4* dst = reinterpret_cast<float4*>(scfd);
        for (int i = tid; i < 1056; i += 256) dst[i] = src[i];
    }
    // A: contiguous float4 load of both partials, summed
    {
        const float4* p0 = reinterpret_cast<const float4*>(g_out217 + bbase * OUTC);
        const float4* p1 = reinterpret_cast<const float4*>(g_out217 + BO + bbase * OUTC);
        float4* d = reinterpret_cast<float4*>(so);
        for (int i = tid; i < RB_OUTF / 4; i += 256) {
            float4 a = p0[i], b = p1[i];
            d[i] = make_float4(a.x + b.x, a.y + b.y, a.z + b.z, a.w + b.w);
        }
    }
    __syncthreads();

    // y0 / goal / gy0
    if (tid < RB_ROWS) {
        int b = tid / NDOF, dof = tid - b * NDOF;
        float y0 = state[bbase * NDOF + tid];
        float goal = so[b * OUTC + dof];
        su[1 * RB_ROWS + tid] = y0;
        su[2 * RB_ROWS + tid] = goal;
        sg[tid] = goal - y0;
    }
    __syncthreads();

    // U-build: thread = (g, r) constant; n = g + 4*i loop, stride-constant addrs
    if (tid < 4 * RB_ROWS) {
        const int g = tid / RB_ROWS;          // 0..3
        const int r = tid - g * RB_ROWS;      // 0..55
        const int b = r / NDOF, dof = r - b * NDOF;
        const float sgr = sg[r];
        const float* wsrc = so + b * OUTC + NDOF + dof * NB + g;
        float* udst = su + (3 + g) * RB_ROWS + r;
#pragma unroll
        for (int i = 0; i < 8; i++) {
            int n = g + 4 * i;
            if (n < NB) udst[4 * i * RB_ROWS] = wsrc[4 * i] * sgr;
        }
    }
    __syncthreads();

    // C: y[row][s] = alpha[s] + sum_{ch>=1} U[row][ch]*coef[s][ch]
    if (tid < 224) {
        const int grp = tid / 28;             // 0..7 sample group
        const int rp  = tid - grp * 28;       // row pair: rows rp*2, rp*2+1
        const float2* cfb = scfd + grp * 8;   // base, +ch*64 per channel
        const float*  ub  = su + rp * 2;      // base, +ch*56 per channel

        ull acc[7];
        {   // alpha (ch 0, u == 1)
            const float4* c4 = reinterpret_cast<const float4*>(cfb);
            float4 c0 = c4[0], c1 = c4[1], c2 = c4[2], c3 = c4[3];
            acc[0] = *reinterpret_cast<const ull*>(&c0.x);
            acc[1] = *reinterpret_cast<const ull*>(&c0.z);
            acc[2] = *reinterpret_cast<const ull*>(&c1.x);
            acc[3] = *reinterpret_cast<const ull*>(&c1.z);
            acc[4] = *reinterpret_cast<const ull*>(&c2.x);
            acc[5] = *reinterpret_cast<const ull*>(&c2.z);
            acc[6] = *reinterpret_cast<const ull*>(&c3.x);
        }
#pragma unroll
        for (int ch = 1; ch < 33; ch++) {
            ull u = *reinterpret_cast<const ull*>(ub + ch * RB_ROWS);
            const float4* c4 = reinterpret_cast<const float4*>(cfb + ch * 64);
            float4 c0 = c4[0], c1 = c4[1], c2 = c4[2], c3 = c4[3];
            fma2(acc[0], u, *reinterpret_cast<const ull*>(&c0.x));
            fma2(acc[1], u, *reinterpret_cast<const ull*>(&c0.z));
            fma2(acc[2], u, *reinterpret_cast<const ull*>(&c1.x));
            fma2(acc[3], u, *reinterpret_cast<const ull*>(&c1.z));
            fma2(acc[4], u, *reinterpret_cast<const ull*>(&c2.x));
            fma2(acc[5], u, *reinterpret_cast<const ull*>(&c2.z));
            fma2(acc[6], u, *reinterpret_cast<const ull*>(&c3.x));
        }
        __syncthreads();   // so -> ybuf reuse

        const int s0 = grp * 7;
        const int cnt = (grp == 7) ? 2 : 7;
#pragma unroll
        for (int p = 0; p < 2; p++) {
            int row = rp * 2 + p;
            int b = row / NDOF, dof = row - b * NDOF;
            float* yb = ybuf + b * (NS * NDOF) + dof + s0 * NDOF;
#pragma unroll
            for (int q = 0; q < 7; q++) {
                if (q < cnt) {
                    float v = p ? hi32(acc[q]) : lo32(acc[q]);
                    yb[q * NDOF] = v;
                }
            }
        }
    } else {
        __syncthreads();
    }
    __syncthreads();

    // D: contiguous float4 store of the block's output slice
    {
        const float4* s4 = reinterpret_cast<const float4*>(ybuf);
        float4* d4 = reinterpret_cast<float4*>(out + (size_t)blockIdx.x * RB_YF);
        for (int i = tid; i < RB_YF / 4; i += 256) d4[i] = s4[i];
    }
}

// ---------------------------------------------------------------------------
extern "C" void kernel_launch(void* const* d_in, const int* in_sizes, int n_in,
                              void* d_out, int out_size) {
    const float* x      = (const float*)d_in[0];
    const float* state  = (const float*)d_in[1];
    const float* W_pt   = (const float*)d_in[2];
    const float* b_pt   = (const float*)d_in[3];
    const float* W_last = (const float*)d_in[4];
    const float* b_last = (const float*)d_in[5];
    const float* c      = (const float*)d_in[6];
    const float* h      = (const float*)d_in[7];
    float* out = (float*)d_out;

    const int coef_smem = (NB * GW + GW + 2 * NB) * (int)sizeof(float);

    static cudaStream_t s2;
    static cudaEvent_t evFork, evJoin;
    static int init_done = 0;
    if (!init_done) {
        cudaFuncSetAttribute(coef_kernel, cudaFuncAttributeMaxDynamicSharedMemorySize,
                             coef_smem);
        cudaFuncSetAttribute(rollout_kernel, cudaFuncAttributeMaxDynamicSharedMemorySize,
                             RB_SMEM);
        cudaStreamCreateWithFlags(&s2, cudaStreamNonBlocking);
        cudaEventCreateWithFlags(&evFork, cudaEventDisableTiming);
        cudaEventCreateWithFlags(&evJoin, cudaEventDisableTiming);
        init_done = 1;
    }

    // fork: coef runs concurrently with the two GEMMs
    cudaEventRecord(evFork, 0);
    cudaStreamWaitEvent(s2, evFork, 0);
    coef_kernel<<<NS, 256, coef_smem, s2>>>(c, h);
    cudaEventRecord(evJoin, s2);

    gemm1_kernel<<<dim3(BATCH / 64, HID / 64), 256>>>(x, W_pt, b_pt);
    gemm2_kernel<<<dim3(BATCH / 64, 2, 2), 256>>>(W_last, b_last);

    // join: rollout needs both g_coef_t and g_out217 partials
    cudaStreamWaitEvent(0, evJoin, 0);
    rollout_kernel<<<BATCH / RB_BATCH, 256, RB_SMEM>>>(state, out);
}